// round 10
// baseline (speedup 1.0000x reference)
#include <cuda_runtime.h>
#include <cuda_fp16.h>

#define NU 100000
#define NI 50000
#define NN 150000           // NU + NI
#define D  64
#define MAXE 1500000        // interactions
#define NBK 147             // ceil(NN / 1024)

// ---------------- scratch (static device globals) ---------------------------
// y_l = dinv^2 * s  (pre-scaled fp16 operand; r_l = y_l / dinv)
__device__ __half2 g_h0[NN * D / 2];   // layer-0 operand: half(emb * dinv)
__device__ __half2 g_h1[NN * D / 2];
__device__ __half2 g_h2[NN * D / 2];
__device__ int     g_deg [NN];
__device__ float   g_dinv[NN];
__device__ int     g_offs[NN];         // CSR slab start per node
__device__ int     g_cursor[NN];
__device__ int     g_col[2 * MAXE];    // CSR src index (weight-free)
__device__ int     g_tail;             // global slab allocator

// ---------------- setup ------------------------------------------------------
__global__ void k_zero_deg() {
    int i = blockIdx.x * blockDim.x + threadIdx.x;
    if (i < NN) g_deg[i] = 0;
    if (i == 0) g_tail = 0;
}

__global__ void k_count_deg(const int* __restrict__ eu,
                            const int* __restrict__ ei, int ne) {
    int e = blockIdx.x * blockDim.x + threadIdx.x;
    if (e >= ne) return;
    atomicAdd(&g_deg[eu[e]], 1);
    atomicAdd(&g_deg[NU + ei[e]], 1);
}

// Per-block scan + single atomic slab allocation; also computes dinv.
__global__ void k_alloc(int n) {
    __shared__ int sh[1024];
    __shared__ int base;
    int tid = threadIdx.x;
    int i = blockIdx.x * 1024 + tid;
    int v = (i < n) ? g_deg[i] : 0;
    if (i < n) g_dinv[i] = rsqrtf(v > 0 ? (float)v : 1.0f);
    sh[tid] = v;
    __syncthreads();
    for (int off = 1; off < 1024; off <<= 1) {
        int t = (tid >= off) ? sh[tid - off] : 0;
        __syncthreads();
        sh[tid] += t;
        __syncthreads();
    }
    if (tid == 1023) base = atomicAdd(&g_tail, sh[1023]);
    __syncthreads();
    if (i < n) {
        int o = base + sh[tid] - v;    // exclusive within block + slab base
        g_offs[i] = o;
        g_cursor[i] = o;
    }
}

// Fused: blocks [0, FB) fill CSR cols; blocks [FB, FB+PB) prescale h0.
__global__ void k_fill_prescale(const int* __restrict__ eu,
                                const int* __restrict__ ei, int ne,
                                const float* __restrict__ emb, int fb) {
    if ((int)blockIdx.x < fb) {
        int e = blockIdx.x * blockDim.x + threadIdx.x;
        if (e >= ne) return;
        int u  = eu[e];
        int it = NU + ei[e];
        int s1 = atomicAdd(&g_cursor[it], 1);
        g_col[s1] = u;                      // edge user -> item (dst=item)
        int s2 = atomicAdd(&g_cursor[u], 1);
        g_col[s2] = it;                     // edge item -> user (dst=user)
    } else {
        int i = (blockIdx.x - fb) * blockDim.x + threadIdx.x; // NN*32 half2
        if (i >= NN * 32) return;
        int node = i >> 5;
        float dv = g_dinv[node];
        float2 e2 = ((const float2*)emb)[i];
        g_h0[i] = __floats2half2_rn(e2.x * dv, e2.y * dv);
    }
}

// ---------------- SpMM: one warp per node, 4 edges per LDG.128 ---------------
// lane = group(0..3: edge-in-chunk) x sub(0..7: 16B row segment)
// s = sum_{e: dst=v} y_{l-1}[col_e];  y_l[v] = half(dinv^2 * s)
template<int LAYER>
__global__ void k_spmm() {
    int node = (blockIdx.x * blockDim.x + threadIdx.x) >> 5;
    if (node >= NN) return;
    int lane = threadIdx.x & 31;
    int group = lane >> 3;
    int sub   = lane & 7;

    const uint4* __restrict__ src4 = (const uint4*)((LAYER == 0) ? g_h0 : g_h1);
    uint4* __restrict__ dst4       = (uint4*)((LAYER == 0) ? g_h1 : g_h2);

    int beg = g_offs[node];
    int end = beg + g_deg[node];

    float a0=0.f,a1=0.f,a2=0.f,a3=0.f,a4=0.f,a5=0.f,a6=0.f,a7=0.f;

    for (int base = beg; base < end; base += 32) {
        int j = base + lane;
        int mycol = (j < end) ? g_col[j] : 0;    // coalesced: 1 LDG / 32 edges
        int cnt = end - base;
        if (cnt > 32) cnt = 32;

        int i = 0;
        #pragma unroll 2
        for (; i + 3 < cnt; i += 4) {
            int c = __shfl_sync(0xffffffffu, mycol, i + group);
            uint4 v = src4[c * 8 + sub];
            float2 f0 = __half22float2(*(const __half2*)&v.x);
            float2 f1 = __half22float2(*(const __half2*)&v.y);
            float2 f2 = __half22float2(*(const __half2*)&v.z);
            float2 f3 = __half22float2(*(const __half2*)&v.w);
            a0 += f0.x; a1 += f0.y; a2 += f1.x; a3 += f1.y;
            a4 += f2.x; a5 += f2.y; a6 += f3.x; a7 += f3.y;
        }
        if (i < cnt) {
            int e = i + group;
            int c = __shfl_sync(0xffffffffu, mycol, e & 31);
            if (e < cnt) {
                uint4 v = src4[c * 8 + sub];
                float2 f0 = __half22float2(*(const __half2*)&v.x);
                float2 f1 = __half22float2(*(const __half2*)&v.y);
                float2 f2 = __half22float2(*(const __half2*)&v.z);
                float2 f3 = __half22float2(*(const __half2*)&v.w);
                a0 += f0.x; a1 += f0.y; a2 += f1.x; a3 += f1.y;
                a4 += f2.x; a5 += f2.y; a6 += f3.x; a7 += f3.y;
            }
        }
    }

    #pragma unroll
    for (int off = 8; off <= 16; off <<= 1) {
        a0 += __shfl_xor_sync(0xffffffffu, a0, off);
        a1 += __shfl_xor_sync(0xffffffffu, a1, off);
        a2 += __shfl_xor_sync(0xffffffffu, a2, off);
        a3 += __shfl_xor_sync(0xffffffffu, a3, off);
        a4 += __shfl_xor_sync(0xffffffffu, a4, off);
        a5 += __shfl_xor_sync(0xffffffffu, a5, off);
        a6 += __shfl_xor_sync(0xffffffffu, a6, off);
        a7 += __shfl_xor_sync(0xffffffffu, a7, off);
    }

    if (lane < 8) {
        float dv = g_dinv[node];
        float d2 = dv * dv;
        __half2 h0 = __floats2half2_rn(d2 * a0, d2 * a1);
        __half2 h1 = __floats2half2_rn(d2 * a2, d2 * a3);
        __half2 h2 = __floats2half2_rn(d2 * a4, d2 * a5);
        __half2 h3 = __floats2half2_rn(d2 * a6, d2 * a7);
        uint4 o;
        o.x = *(const unsigned int*)&h0;
        o.y = *(const unsigned int*)&h1;
        o.z = *(const unsigned int*)&h2;
        o.w = *(const unsigned int*)&h3;
        dst4[node * 8 + sub] = o;
    }
}

// ---------------- layer 3 (sampled nodes only) + epilogue --------------------
// One warp per output row (3*batch rows). Gathers neighbors from h2 (fp32 s),
// r3 = dinv*s; r1,r2 reconstructed from h1,h2; out=(emb+r1+r2+r3)/4.
// t==0 warps additionally compute the l2 norms.
__global__ void k_spmm_out(const int* __restrict__ users,
                           const int* __restrict__ pos,
                           const int* __restrict__ neg,
                           const float* __restrict__ emb,
                           float* __restrict__ out, int batch) {
    int w = (blockIdx.x * blockDim.x + threadIdx.x) >> 5;
    if (w >= 3 * batch) return;
    int t = w / batch;
    int b = w - t * batch;
    int lane = threadIdx.x & 31;
    int group = lane >> 3;
    int sub   = lane & 7;

    int node = (t == 0) ? users[b] : (t == 1) ? (NU + pos[b]) : (NU + neg[b]);

    const uint4* __restrict__ src4 = (const uint4*)g_h2;
    int beg = g_offs[node];
    int end = beg + g_deg[node];

    float a0=0.f,a1=0.f,a2=0.f,a3=0.f,a4=0.f,a5=0.f,a6=0.f,a7=0.f;
    for (int base = beg; base < end; base += 32) {
        int j = base + lane;
        int mycol = (j < end) ? g_col[j] : 0;
        int cnt = end - base;
        if (cnt > 32) cnt = 32;
        for (int i = 0; i < cnt; i += 4) {
            int e = i + group;
            int c = __shfl_sync(0xffffffffu, mycol, e & 31);
            if (e < cnt) {
                uint4 v = src4[c * 8 + sub];
                float2 f0 = __half22float2(*(const __half2*)&v.x);
                float2 f1 = __half22float2(*(const __half2*)&v.y);
                float2 f2 = __half22float2(*(const __half2*)&v.z);
                float2 f3 = __half22float2(*(const __half2*)&v.w);
                a0 += f0.x; a1 += f0.y; a2 += f1.x; a3 += f1.y;
                a4 += f2.x; a5 += f2.y; a6 += f3.x; a7 += f3.y;
            }
        }
    }
    #pragma unroll
    for (int off = 8; off <= 16; off <<= 1) {
        a0 += __shfl_xor_sync(0xffffffffu, a0, off);
        a1 += __shfl_xor_sync(0xffffffffu, a1, off);
        a2 += __shfl_xor_sync(0xffffffffu, a2, off);
        a3 += __shfl_xor_sync(0xffffffffu, a3, off);
        a4 += __shfl_xor_sync(0xffffffffu, a4, off);
        a5 += __shfl_xor_sync(0xffffffffu, a5, off);
        a6 += __shfl_xor_sync(0xffffffffu, a6, off);
        a7 += __shfl_xor_sync(0xffffffffu, a7, off);
    }

    float l2part = 0.f;
    if (lane < 8) {
        float dv = g_dinv[node];
        float sd = 1.0f / dv;                   // sqrt(deg)
        // emb segment: 8 fp32 dims = 2 float4
        const float4* e4 = (const float4*)(emb + (size_t)node * D + sub * 8);
        float4 e0 = e4[0], e1 = e4[1];
        // y1, y2 segments (8 halves each)
        uint4 y1v = ((const uint4*)g_h1)[node * 8 + sub];
        uint4 y2v = ((const uint4*)g_h2)[node * 8 + sub];
        float2 p0 = __half22float2(*(const __half2*)&y1v.x);
        float2 p1 = __half22float2(*(const __half2*)&y1v.y);
        float2 p2 = __half22float2(*(const __half2*)&y1v.z);
        float2 p3 = __half22float2(*(const __half2*)&y1v.w);
        float2 q0 = __half22float2(*(const __half2*)&y2v.x);
        float2 q1 = __half22float2(*(const __half2*)&y2v.y);
        float2 q2 = __half22float2(*(const __half2*)&y2v.z);
        float2 q3 = __half22float2(*(const __half2*)&y2v.w);

        float4 o0, o1;
        o0.x = (e0.x + sd * (p0.x + q0.x) + dv * a0) * 0.25f;
        o0.y = (e0.y + sd * (p0.y + q0.y) + dv * a1) * 0.25f;
        o0.z = (e0.z + sd * (p1.x + q1.x) + dv * a2) * 0.25f;
        o0.w = (e0.w + sd * (p1.y + q1.y) + dv * a3) * 0.25f;
        o1.x = (e1.x + sd * (p2.x + q2.x) + dv * a4) * 0.25f;
        o1.y = (e1.y + sd * (p2.y + q2.y) + dv * a5) * 0.25f;
        o1.z = (e1.z + sd * (p3.x + q3.x) + dv * a6) * 0.25f;
        o1.w = (e1.w + sd * (p3.y + q3.y) + dv * a7) * 0.25f;
        float4* od = (float4*)(out + (size_t)t * batch * D + (size_t)b * D + sub * 8);
        od[0] = o0;
        od[1] = o1;

        if (t == 0) {
            // l2 needs emb of u (have it), p, n
            int pn = NU + pos[b];
            int nn = NU + neg[b];
            const float4* pp = (const float4*)(emb + (size_t)pn * D + sub * 8);
            const float4* np = (const float4*)(emb + (size_t)nn * D + sub * 8);
            float4 pe0 = pp[0], pe1 = pp[1];
            float4 ne0 = np[0], ne1 = np[1];
            l2part = e0.x*e0.x + e0.y*e0.y + e0.z*e0.z + e0.w*e0.w
                   + e1.x*e1.x + e1.y*e1.y + e1.z*e1.z + e1.w*e1.w
                   + pe0.x*pe0.x + pe0.y*pe0.y + pe0.z*pe0.z + pe0.w*pe0.w
                   + pe1.x*pe1.x + pe1.y*pe1.y + pe1.z*pe1.z + pe1.w*pe1.w
                   + ne0.x*ne0.x + ne0.y*ne0.y + ne0.z*ne0.z + ne0.w*ne0.w
                   + ne1.x*ne1.x + ne1.y*ne1.y + ne1.z*ne1.z + ne1.w*ne1.w;
        }
    }
    if (t == 0) {
        // reduce l2part across lanes 0..7
        l2part += __shfl_down_sync(0xffffffffu, l2part, 4);
        l2part += __shfl_down_sync(0xffffffffu, l2part, 2);
        l2part += __shfl_down_sync(0xffffffffu, l2part, 1);
        if (lane == 0)
            out[(size_t)3 * batch * D + b] = l2part;
    }
}

// ---------------- launch -----------------------------------------------------
extern "C" void kernel_launch(void* const* d_in, const int* in_sizes, int n_in,
                              void* d_out, int out_size) {
    const float* emb   = (const float*)d_in[0];
    const int*   eu    = (const int*)  d_in[1];
    const int*   ei    = (const int*)  d_in[2];
    const int*   users = (const int*)  d_in[3];
    const int*   pos   = (const int*)  d_in[4];
    const int*   neg   = (const int*)  d_in[5];
    int ne    = in_sizes[1];
    int batch = in_sizes[3];
    float* out = (float*)d_out;

    // 1) degrees
    k_zero_deg<<<(NN + 255) / 256, 256>>>();
    k_count_deg<<<(ne + 255) / 256, 256>>>(eu, ei, ne);

    // 2) slab allocation (block scan + one atomic) + dinv + cursors
    k_alloc<<<NBK, 1024>>>(NN);

    // 3) CSR fill + prescaled fp16 embedding (fused launch)
    int fb = (ne + 255) / 256;
    int pb = (NN * 32 + 255) / 256;
    k_fill_prescale<<<fb + pb, 256>>>(eu, ei, ne, emb, fb);

    // 4) two full-graph propagation layers
    int spmm_blocks = (NN * 32 + 255) / 256;
    k_spmm<0><<<spmm_blocks, 256>>>();   // h0 -> h1
    k_spmm<1><<<spmm_blocks, 256>>>();   // h1 -> h2

    // 5) layer 3 only at sampled nodes, fused with epilogue + l2
    int ow = 3 * batch;
    k_spmm_out<<<(ow * 32 + 255) / 256, 256>>>(users, pos, neg, emb, out, batch);
}

// round 11
// speedup vs baseline: 1.0011x; 1.0011x over previous
#include <cuda_runtime.h>
#include <cuda_fp16.h>

#define NU 100000
#define NI 50000
#define NN 150000           // NU + NI
#define D  64
#define MAXE 1500000        // interactions
#define NBK 147             // ceil(NN / 1024)

// ---------------- scratch (static device globals) ---------------------------
// y_l = dinv^2 * s  (pre-scaled fp16 operand; r_l = y_l / dinv)
__device__ __half2 g_h0[NN * D / 2];   // layer-0 operand: half(emb * dinv)
__device__ __half2 g_h1[NN * D / 2];
__device__ __half2 g_h2[NN * D / 2];
__device__ int     g_deg [NN];
__device__ float   g_dinv[NN];
__device__ int     g_offs[NN];         // CSR slab start per node
__device__ int     g_cursor[NN];
__device__ int     g_col[2 * MAXE];    // CSR src index (weight-free)
__device__ int     g_tail;             // global slab allocator

// ---------------- setup ------------------------------------------------------
__global__ void k_zero_deg() {
    int i = blockIdx.x * blockDim.x + threadIdx.x;
    if (i < NN) g_deg[i] = 0;
    if (i == 0) g_tail = 0;
}

__global__ void k_count_deg(const int* __restrict__ eu,
                            const int* __restrict__ ei, int ne) {
    int e = blockIdx.x * blockDim.x + threadIdx.x;
    if (e >= ne) return;
    atomicAdd(&g_deg[eu[e]], 1);
    atomicAdd(&g_deg[NU + ei[e]], 1);
}

// Per-block scan + single atomic slab allocation; also computes dinv.
__global__ void k_alloc(int n) {
    __shared__ int sh[1024];
    __shared__ int base;
    int tid = threadIdx.x;
    int i = blockIdx.x * 1024 + tid;
    int v = (i < n) ? g_deg[i] : 0;
    if (i < n) g_dinv[i] = rsqrtf(v > 0 ? (float)v : 1.0f);
    sh[tid] = v;
    __syncthreads();
    for (int off = 1; off < 1024; off <<= 1) {
        int t = (tid >= off) ? sh[tid - off] : 0;
        __syncthreads();
        sh[tid] += t;
        __syncthreads();
    }
    if (tid == 1023) base = atomicAdd(&g_tail, sh[1023]);
    __syncthreads();
    if (i < n) {
        int o = base + sh[tid] - v;    // exclusive within block + slab base
        g_offs[i] = o;
        g_cursor[i] = o;
    }
}

// Fused: blocks [0, FB) fill CSR cols; blocks [FB, FB+PB) prescale h0.
__global__ void k_fill_prescale(const int* __restrict__ eu,
                                const int* __restrict__ ei, int ne,
                                const float* __restrict__ emb, int fb) {
    if ((int)blockIdx.x < fb) {
        int e = blockIdx.x * blockDim.x + threadIdx.x;
        if (e >= ne) return;
        int u  = eu[e];
        int it = NU + ei[e];
        int s1 = atomicAdd(&g_cursor[it], 1);
        g_col[s1] = u;                      // edge user -> item (dst=item)
        int s2 = atomicAdd(&g_cursor[u], 1);
        g_col[s2] = it;                     // edge item -> user (dst=user)
    } else {
        int i = (blockIdx.x - fb) * blockDim.x + threadIdx.x; // NN*32 half2
        if (i >= NN * 32) return;
        int node = i >> 5;
        float dv = g_dinv[node];
        float2 e2 = ((const float2*)emb)[i];
        g_h0[i] = __floats2half2_rn(e2.x * dv, e2.y * dv);
    }
}

// ---------------- SpMM: one warp per node, 4 edges per LDG.128 ---------------
// lane = group(0..3: edge-in-chunk) x sub(0..7: 16B row segment)
// s = sum_{e: dst=v} y_{l-1}[col_e];  y_l[v] = half(dinv^2 * s)
template<int LAYER>
__global__ void k_spmm() {
    int node = (blockIdx.x * blockDim.x + threadIdx.x) >> 5;
    if (node >= NN) return;
    int lane = threadIdx.x & 31;
    int group = lane >> 3;
    int sub   = lane & 7;

    const uint4* __restrict__ src4 = (const uint4*)((LAYER == 0) ? g_h0 : g_h1);
    uint4* __restrict__ dst4       = (uint4*)((LAYER == 0) ? g_h1 : g_h2);

    int beg = g_offs[node];
    int end = beg + g_deg[node];

    float a0=0.f,a1=0.f,a2=0.f,a3=0.f,a4=0.f,a5=0.f,a6=0.f,a7=0.f;

    for (int base = beg; base < end; base += 32) {
        int j = base + lane;
        int mycol = (j < end) ? g_col[j] : 0;    // coalesced: 1 LDG / 32 edges
        int cnt = end - base;
        if (cnt > 32) cnt = 32;

        int i = 0;
        #pragma unroll 2
        for (; i + 3 < cnt; i += 4) {
            int c = __shfl_sync(0xffffffffu, mycol, i + group);
            uint4 v = src4[c * 8 + sub];
            float2 f0 = __half22float2(*(const __half2*)&v.x);
            float2 f1 = __half22float2(*(const __half2*)&v.y);
            float2 f2 = __half22float2(*(const __half2*)&v.z);
            float2 f3 = __half22float2(*(const __half2*)&v.w);
            a0 += f0.x; a1 += f0.y; a2 += f1.x; a3 += f1.y;
            a4 += f2.x; a5 += f2.y; a6 += f3.x; a7 += f3.y;
        }
        if (i < cnt) {
            int e = i + group;
            int c = __shfl_sync(0xffffffffu, mycol, e & 31);
            if (e < cnt) {
                uint4 v = src4[c * 8 + sub];
                float2 f0 = __half22float2(*(const __half2*)&v.x);
                float2 f1 = __half22float2(*(const __half2*)&v.y);
                float2 f2 = __half22float2(*(const __half2*)&v.z);
                float2 f3 = __half22float2(*(const __half2*)&v.w);
                a0 += f0.x; a1 += f0.y; a2 += f1.x; a3 += f1.y;
                a4 += f2.x; a5 += f2.y; a6 += f3.x; a7 += f3.y;
            }
        }
    }

    #pragma unroll
    for (int off = 8; off <= 16; off <<= 1) {
        a0 += __shfl_xor_sync(0xffffffffu, a0, off);
        a1 += __shfl_xor_sync(0xffffffffu, a1, off);
        a2 += __shfl_xor_sync(0xffffffffu, a2, off);
        a3 += __shfl_xor_sync(0xffffffffu, a3, off);
        a4 += __shfl_xor_sync(0xffffffffu, a4, off);
        a5 += __shfl_xor_sync(0xffffffffu, a5, off);
        a6 += __shfl_xor_sync(0xffffffffu, a6, off);
        a7 += __shfl_xor_sync(0xffffffffu, a7, off);
    }

    if (lane < 8) {
        float dv = g_dinv[node];
        float d2 = dv * dv;
        __half2 h0 = __floats2half2_rn(d2 * a0, d2 * a1);
        __half2 h1 = __floats2half2_rn(d2 * a2, d2 * a3);
        __half2 h2 = __floats2half2_rn(d2 * a4, d2 * a5);
        __half2 h3 = __floats2half2_rn(d2 * a6, d2 * a7);
        uint4 o;
        o.x = *(const unsigned int*)&h0;
        o.y = *(const unsigned int*)&h1;
        o.z = *(const unsigned int*)&h2;
        o.w = *(const unsigned int*)&h3;
        dst4[node * 8 + sub] = o;
    }
}

// ---------------- layer 3 (sampled nodes only) + epilogue --------------------
// One warp per output row (3*batch rows). Gathers neighbors from h2 (fp32 s),
// r3 = dinv*s; r1,r2 reconstructed from h1,h2; out=(emb+r1+r2+r3)/4.
// t==0 warps additionally compute the l2 norms.
__global__ void k_spmm_out(const int* __restrict__ users,
                           const int* __restrict__ pos,
                           const int* __restrict__ neg,
                           const float* __restrict__ emb,
                           float* __restrict__ out, int batch) {
    int w = (blockIdx.x * blockDim.x + threadIdx.x) >> 5;
    if (w >= 3 * batch) return;
    int t = w / batch;
    int b = w - t * batch;
    int lane = threadIdx.x & 31;
    int group = lane >> 3;
    int sub   = lane & 7;

    int node = (t == 0) ? users[b] : (t == 1) ? (NU + pos[b]) : (NU + neg[b]);

    const uint4* __restrict__ src4 = (const uint4*)g_h2;
    int beg = g_offs[node];
    int end = beg + g_deg[node];

    float a0=0.f,a1=0.f,a2=0.f,a3=0.f,a4=0.f,a5=0.f,a6=0.f,a7=0.f;
    for (int base = beg; base < end; base += 32) {
        int j = base + lane;
        int mycol = (j < end) ? g_col[j] : 0;
        int cnt = end - base;
        if (cnt > 32) cnt = 32;
        for (int i = 0; i < cnt; i += 4) {
            int e = i + group;
            int c = __shfl_sync(0xffffffffu, mycol, e & 31);
            if (e < cnt) {
                uint4 v = src4[c * 8 + sub];
                float2 f0 = __half22float2(*(const __half2*)&v.x);
                float2 f1 = __half22float2(*(const __half2*)&v.y);
                float2 f2 = __half22float2(*(const __half2*)&v.z);
                float2 f3 = __half22float2(*(const __half2*)&v.w);
                a0 += f0.x; a1 += f0.y; a2 += f1.x; a3 += f1.y;
                a4 += f2.x; a5 += f2.y; a6 += f3.x; a7 += f3.y;
            }
        }
    }
    #pragma unroll
    for (int off = 8; off <= 16; off <<= 1) {
        a0 += __shfl_xor_sync(0xffffffffu, a0, off);
        a1 += __shfl_xor_sync(0xffffffffu, a1, off);
        a2 += __shfl_xor_sync(0xffffffffu, a2, off);
        a3 += __shfl_xor_sync(0xffffffffu, a3, off);
        a4 += __shfl_xor_sync(0xffffffffu, a4, off);
        a5 += __shfl_xor_sync(0xffffffffu, a5, off);
        a6 += __shfl_xor_sync(0xffffffffu, a6, off);
        a7 += __shfl_xor_sync(0xffffffffu, a7, off);
    }

    float l2part = 0.f;
    if (lane < 8) {
        float dv = g_dinv[node];
        float sd = 1.0f / dv;                   // sqrt(deg)
        // emb segment: 8 fp32 dims = 2 float4
        const float4* e4 = (const float4*)(emb + (size_t)node * D + sub * 8);
        float4 e0 = e4[0], e1 = e4[1];
        // y1, y2 segments (8 halves each)
        uint4 y1v = ((const uint4*)g_h1)[node * 8 + sub];
        uint4 y2v = ((const uint4*)g_h2)[node * 8 + sub];
        float2 p0 = __half22float2(*(const __half2*)&y1v.x);
        float2 p1 = __half22float2(*(const __half2*)&y1v.y);
        float2 p2 = __half22float2(*(const __half2*)&y1v.z);
        float2 p3 = __half22float2(*(const __half2*)&y1v.w);
        float2 q0 = __half22float2(*(const __half2*)&y2v.x);
        float2 q1 = __half22float2(*(const __half2*)&y2v.y);
        float2 q2 = __half22float2(*(const __half2*)&y2v.z);
        float2 q3 = __half22float2(*(const __half2*)&y2v.w);

        float4 o0, o1;
        o0.x = (e0.x + sd * (p0.x + q0.x) + dv * a0) * 0.25f;
        o0.y = (e0.y + sd * (p0.y + q0.y) + dv * a1) * 0.25f;
        o0.z = (e0.z + sd * (p1.x + q1.x) + dv * a2) * 0.25f;
        o0.w = (e0.w + sd * (p1.y + q1.y) + dv * a3) * 0.25f;
        o1.x = (e1.x + sd * (p2.x + q2.x) + dv * a4) * 0.25f;
        o1.y = (e1.y + sd * (p2.y + q2.y) + dv * a5) * 0.25f;
        o1.z = (e1.z + sd * (p3.x + q3.x) + dv * a6) * 0.25f;
        o1.w = (e1.w + sd * (p3.y + q3.y) + dv * a7) * 0.25f;
        float4* od = (float4*)(out + (size_t)t * batch * D + (size_t)b * D + sub * 8);
        od[0] = o0;
        od[1] = o1;

        if (t == 0) {
            // l2 needs emb of u (have it), p, n
            int pn = NU + pos[b];
            int nn = NU + neg[b];
            const float4* pp = (const float4*)(emb + (size_t)pn * D + sub * 8);
            const float4* np = (const float4*)(emb + (size_t)nn * D + sub * 8);
            float4 pe0 = pp[0], pe1 = pp[1];
            float4 ne0 = np[0], ne1 = np[1];
            l2part = e0.x*e0.x + e0.y*e0.y + e0.z*e0.z + e0.w*e0.w
                   + e1.x*e1.x + e1.y*e1.y + e1.z*e1.z + e1.w*e1.w
                   + pe0.x*pe0.x + pe0.y*pe0.y + pe0.z*pe0.z + pe0.w*pe0.w
                   + pe1.x*pe1.x + pe1.y*pe1.y + pe1.z*pe1.z + pe1.w*pe1.w
                   + ne0.x*ne0.x + ne0.y*ne0.y + ne0.z*ne0.z + ne0.w*ne0.w
                   + ne1.x*ne1.x + ne1.y*ne1.y + ne1.z*ne1.z + ne1.w*ne1.w;
        }
    }
    if (t == 0) {
        // reduce l2part across lanes 0..7
        l2part += __shfl_down_sync(0xffffffffu, l2part, 4);
        l2part += __shfl_down_sync(0xffffffffu, l2part, 2);
        l2part += __shfl_down_sync(0xffffffffu, l2part, 1);
        if (lane == 0)
            out[(size_t)3 * batch * D + b] = l2part;
    }
}

// ---------------- launch -----------------------------------------------------
extern "C" void kernel_launch(void* const* d_in, const int* in_sizes, int n_in,
                              void* d_out, int out_size) {
    const float* emb   = (const float*)d_in[0];
    const int*   eu    = (const int*)  d_in[1];
    const int*   ei    = (const int*)  d_in[2];
    const int*   users = (const int*)  d_in[3];
    const int*   pos   = (const int*)  d_in[4];
    const int*   neg   = (const int*)  d_in[5];
    int ne    = in_sizes[1];
    int batch = in_sizes[3];
    float* out = (float*)d_out;

    // 1) degrees
    k_zero_deg<<<(NN + 255) / 256, 256>>>();
    k_count_deg<<<(ne + 255) / 256, 256>>>(eu, ei, ne);

    // 2) slab allocation (block scan + one atomic) + dinv + cursors
    k_alloc<<<NBK, 1024>>>(NN);

    // 3) CSR fill + prescaled fp16 embedding (fused launch)
    int fb = (ne + 255) / 256;
    int pb = (NN * 32 + 255) / 256;
    k_fill_prescale<<<fb + pb, 256>>>(eu, ei, ne, emb, fb);

    // 4) two full-graph propagation layers
    int spmm_blocks = (NN * 32 + 255) / 256;
    k_spmm<0><<<spmm_blocks, 256>>>();   // h0 -> h1
    k_spmm<1><<<spmm_blocks, 256>>>();   // h1 -> h2

    // 5) layer 3 only at sampled nodes, fused with epilogue + l2
    int ow = 3 * batch;
    k_spmm_out<<<(ow * 32 + 255) / 256, 256>>>(users, pos, neg, emb, out, batch);
}